// round 8
// baseline (speedup 1.0000x reference)
#include <cuda_runtime.h>
#include <math.h>

typedef unsigned long long u64;

// ---------------- problem constants ----------------
#define B_    256
#define T_    64
#define ACT_  6
#define EMB_  1024
#define S_    32
#define D_    32
#define SF_   1024              // S*D
#define DET_  600
#define HID_  600
#define G3_   1800              // 3*DET
#define OUTW_ 4696              // 4*SF + DET
// out layout per (b,t): [logit_post 0..1024) [stoch_post 1024..2048) [deter 2048..2648)
//                       [logit_prior 2648..3672) [stoch_prior 3672..4696)

// packed dual-fp32 FMA: d = {d.lo + a.lo*b.lo, d.hi + a.hi*b.hi}, IEEE rn per lane
#define FFMA2(d, a, b) asm("fma.rn.f32x2 %0, %1, %2, %0;" : "+l"(d) : "l"(a), "l"(b))
// pack {f, f} into a 64-bit operand (one SASS MOV)
#define PACKDUP(out, f) asm("mov.b64 %0, {%1, %1};" : "=l"(out) : "r"(__float_as_uint(f)))

// ---------------- device scratch (no allocs allowed) ----------------
__device__ float g_E[(size_t)B_ * T_ * HID_];   // embed @ W_obs1[600:] + b_obs1
__device__ float g_x[B_ * HID_];
__device__ float g_deter[B_ * DET_];
__device__ float g_gx[B_ * G3_];
__device__ float g_gh[B_ * G3_];
__device__ float g_y[B_ * HID_];
__device__ float g_o[B_ * HID_];
__device__ int   g_idx[B_ * S_];

// ---------------- GEMM args ----------------
// C[m,n] = act( sum_k A[m,k]*W[k,n] + add[m*addStride + n] )
// If noise != nullptr (requires BN=64, N=1024): fused Gumbel-max sampling.
struct GArgs {
    const float* A; int lda;
    const float* W; int ldw;
    const float* add; long addStride;   // 0 => bias[n]
    float* C; long cStride;
    int act;                            // 0 none, 1 elu
    const float* noise;                 // gumbel noise base or nullptr
    float* onehot;                      // one-hot destination base
    int* idxout;                        // carry indices (post only) or nullptr
    int t;                              // timestep (for noise indexing)
};

// ---------------- fp32 GEMM: BM=32, BK=16, 128 threads, FFMA2 inner loop ----
// Smem tiles double-buffered; register fragments double-buffered. Accumulators
// are packed PAIRS ALONG M, so the packed A operand {a_m, a_m+1} is the natural
// float2 of the transposed As[k][m] tile (no extra smem traffic, no A MOVs).
// B scalars are broadcast into {b,b} pairs with one MOV each.
template<int BN>
__global__ __launch_bounds__(128) void gemm_k(GArgs ga, GArgs gb, int M, int N, int K)
{
    constexpr int TN = BN / 16;         // 4 or 2
    constexpr int ASTR = 36;            // As row stride (pad)
    constexpr int WSTR = BN + 4;
    constexpr int WL = BN / 32;         // float4 W loads per thread per tile

    const GArgs g = (blockIdx.z == 0) ? ga : gb;

    __shared__ __align__(16) float As[2][16][ASTR];   // As[k][m] (transposed)
    __shared__ __align__(16) float Ws[2][16][WSTR];   // Ws[k][n]

    const int tid = threadIdx.x;
    const int m0 = blockIdx.y * 32;
    const int n0 = blockIdx.x * BN;

    const int am = tid >> 2;            // 0..31
    const int ak = (tid & 3) * 4;       // 0,4,8,12
    const int tm = (tid >> 4) * 4;      // 0..28
    const int tn = (tid & 15) * TN;     // 0..BN-TN

    const int ntiles = (K + 15) >> 4;

    float4 rA;
    float4 rW[WL];
    const float* Abase = g.A + (long)(m0 + am) * g.lda + ak;

    auto loadTile = [&](int kt) {
        const int k0 = kt << 4;
        if (k0 + ak < K) rA = *(const float4*)(Abase + k0);
        else             rA = make_float4(0.f, 0.f, 0.f, 0.f);
#pragma unroll
        for (int l = 0; l < WL; l++) {
            int idx = tid + l * 128;
            int wk = idx / (BN / 4);
            int wn = (idx % (BN / 4)) * 4;
            int kk = k0 + wk, nn = n0 + wn;
            if (kk < K && nn < N) rW[l] = *(const float4*)(g.W + (long)kk * g.ldw + nn);
            else                  rW[l] = make_float4(0.f, 0.f, 0.f, 0.f);
        }
    };
    auto storeTile = [&](int buf) {
        As[buf][ak + 0][am] = rA.x;
        As[buf][ak + 1][am] = rA.y;
        As[buf][ak + 2][am] = rA.z;
        As[buf][ak + 3][am] = rA.w;
#pragma unroll
        for (int l = 0; l < WL; l++) {
            int idx = tid + l * 128;
            int wk = idx / (BN / 4);
            int wn = (idx % (BN / 4)) * 4;
            *(float4*)&Ws[buf][wk][wn] = rW[l];
        }
    };

    // packed accumulators: acc[p][j] = { C[tm+2p, tn+j], C[tm+2p+1, tn+j] }
    u64 acc[2][TN];
    {
        float2 z; z.x = 0.f; z.y = 0.f;
        u64 zz = *(u64*)&z;
#pragma unroll
        for (int p = 0; p < 2; p++)
#pragma unroll
            for (int j = 0; j < TN; j++) acc[p][j] = zz;
    }

    // register fragment double buffer: A as two natural m-pairs, B as scalars
    u64   fa[2][2];
    float fb[2][TN];

    loadTile(0);
    storeTile(0);
    __syncthreads();

    int cur = 0;

    auto ldfrag = [&](int buf, int k) {
        ulonglong2 a2 = *(const ulonglong2*)&As[cur][k][tm];   // {a0,a1},{a2,a3}
        fa[buf][0] = a2.x; fa[buf][1] = a2.y;
        if (TN == 4) {
            float4 b4 = *(const float4*)&Ws[cur][k][tn];
            fb[buf][0] = b4.x; fb[buf][1] = b4.y; fb[buf][2] = b4.z; fb[buf][3] = b4.w;
        } else {
            float2 b2 = *(const float2*)&Ws[cur][k][tn];
            fb[buf][0] = b2.x; fb[buf][1] = b2.y;
        }
    };

    ldfrag(0, 0);

    for (int kt = 0; kt < ntiles; kt++) {
        const bool more = (kt + 1 < ntiles);
        if (more) loadTile(kt + 1);     // global loads overlap compute below
#pragma unroll
        for (int k = 0; k < 16; k++) {
            const int cb = k & 1;
            if (k < 15) ldfrag(cb ^ 1, k + 1);   // prefetch next fragments
#pragma unroll
            for (int j = 0; j < TN; j++) {
                u64 bb;
                PACKDUP(bb, fb[cb][j]);
                FFMA2(acc[0][j], fa[cb][0], bb);
                FFMA2(acc[1][j], fa[cb][1], bb);
            }
        }
        if (more) {
            storeTile(cur ^ 1);
            __syncthreads();
            cur ^= 1;
            ldfrag(0, 0);                // first fragments of the new tile
        }
    }

    // unpack accumulators: vals[i][j], i = m offset 0..3 (consecutive m)
    float vals[4][TN];
#pragma unroll
    for (int p = 0; p < 2; p++)
#pragma unroll
        for (int j = 0; j < TN; j++) {
            float2 f = *(float2*)&acc[p][j];
            vals[2 * p + 0][j] = f.x;
            vals[2 * p + 1][j] = f.y;
        }

    // ---- epilogue: bias/add + activation + store ----
#pragma unroll
    for (int i = 0; i < 4; i++) {
        const long m = m0 + tm + i;
#pragma unroll
        for (int j = 0; j < TN; j++) {
            int n = n0 + tn + j;
            if (n < N) {
                float v = vals[i][j] + g.add[m * g.addStride + n];
                if (g.act) v = (v > 0.f) ? v : expm1f(v);
                vals[i][j] = v;
                g.C[m * g.cStride + n] = v;
            }
        }
    }

    // ---- fused Gumbel-max sampling (BN=64, N=1024; groups of 32 align to tiles) ----
    if (g.noise) {
        const int dbase = tn & 31;      // position within the 32-wide group
#pragma unroll
        for (int i = 0; i < 4; i++) {
            const long m = m0 + tm + i;
            float4 nv4 = *(const float4*)(g.noise + ((long)m * T_ + g.t) * SF_ + n0 + tn);
            float nn[4] = {nv4.x, nv4.y, nv4.z, nv4.w};
            float bv = vals[i][0] + nn[0];
            int bi = dbase;
#pragma unroll
            for (int j = 1; j < TN; j++) {
                float c = vals[i][j] + nn[j];
                if (c > bv) { bv = c; bi = dbase + j; }
            }
            // reduce across the 8 lanes covering this (row, group)
#pragma unroll
            for (int off = 1; off < 8; off <<= 1) {
                float ov = __shfl_xor_sync(0xffffffffu, bv, off);
                int   oi = __shfl_xor_sync(0xffffffffu, bi, off);
                if (ov > bv || (ov == bv && oi < bi)) { bv = ov; bi = oi; }
            }
#pragma unroll
            for (int j = 0; j < TN; j++)
                g.onehot[m * g.cStride + n0 + tn + j] = (dbase + j == bi) ? 1.f : 0.f;
            if (g.idxout && (tid & 7) == 0)
                g.idxout[m * S_ + ((n0 + tn) >> 5)] = bi;
        }
    }
}

// ---------------- step kernels ----------------

// x[b,h] = elu( gather32(W_img1, idx) + action@W_img1[1024:] + b_img1 )
__global__ __launch_bounds__(256) void img1_kernel(const float* __restrict__ action,
                                                   const float* __restrict__ W1,
                                                   const float* __restrict__ b1,
                                                   float* __restrict__ x,
                                                   int t, int first)
{
    const int b = blockIdx.x;
    const int tid = threadIdx.x;
    __shared__ int   sidx[S_];
    __shared__ float sact[ACT_];
    if (!first && tid < S_) sidx[tid] = g_idx[b * S_ + tid];
    if (tid < ACT_) sact[tid] = action[((long)b * T_ + t) * ACT_ + tid];
    __syncthreads();
    for (int h = tid; h < HID_; h += 256) {
        float acc = b1[h];
#pragma unroll
        for (int j = 0; j < ACT_; j++)
            acc = fmaf(sact[j], W1[(1024 + j) * HID_ + h], acc);
        if (!first) {
#pragma unroll 4
            for (int gg = 0; gg < S_; gg++)
                acc += W1[(gg * D_ + sidx[gg]) * HID_ + h];
        }
        x[b * HID_ + h] = (acc > 0.0f) ? acc : expm1f(acc);
    }
}

// GRU gate: deter = z*deter + (1-z)*tanh(xh + r*hh), also write deter to out
__global__ __launch_bounds__(256) void gate_kernel(float* __restrict__ out, int t)
{
    int i = blockIdx.x * 256 + threadIdx.x;
    if (i >= B_ * DET_) return;
    int b = i / DET_, j = i - b * DET_;
    const float* gx = g_gx + b * G3_;
    const float* gh = g_gh + b * G3_;
    float z = 1.0f / (1.0f + expf(-(gx[j] + gh[j])));
    float r = 1.0f / (1.0f + expf(-(gx[600 + j] + gh[600 + j])));
    float cand = tanhf(fmaf(r, gh[1200 + j], gx[1200 + j]));
    float d = g_deter[i];
    float dn = z * d + (1.0f - z) * cand;
    g_deter[i] = dn;
    out[(long)b * (T_ * OUTW_) + (long)t * OUTW_ + 2048 + j] = dn;
}

__global__ void zero_kernel(float* p, int n)
{
    int i = blockIdx.x * 256 + threadIdx.x;
    if (i < n) p[i] = 0.0f;
}

// ---------------- host ----------------
extern "C" void kernel_launch(void* const* d_in, const int* in_sizes, int n_in,
                              void* d_out, int out_size)
{
    (void)in_sizes; (void)n_in; (void)out_size;
    const float* action  = (const float*)d_in[0];
    const float* embed   = (const float*)d_in[1];
    const float* n_img   = (const float*)d_in[2];
    const float* n_obs   = (const float*)d_in[3];
    const float* W_img1  = (const float*)d_in[4];
    const float* b_img1  = (const float*)d_in[5];
    const float* Wx      = (const float*)d_in[6];
    const float* Wh      = (const float*)d_in[7];
    const float* b_in    = (const float*)d_in[8];
    const float* b_rec   = (const float*)d_in[9];
    const float* W_img2  = (const float*)d_in[10];
    const float* b_img2  = (const float*)d_in[11];
    const float* W_img5  = (const float*)d_in[12];
    const float* b_img5  = (const float*)d_in[13];
    const float* W_obs1  = (const float*)d_in[14];
    const float* b_obs1  = (const float*)d_in[15];
    const float* W_obs3  = (const float*)d_in[16];
    const float* b_obs3  = (const float*)d_in[17];
    float* out = (float*)d_out;

    float *pE, *px, *pdet, *pgx, *pgh, *py, *po;
    int* pidx;
    cudaGetSymbolAddress((void**)&pE,   g_E);
    cudaGetSymbolAddress((void**)&px,   g_x);
    cudaGetSymbolAddress((void**)&pdet, g_deter);
    cudaGetSymbolAddress((void**)&pgx,  g_gx);
    cudaGetSymbolAddress((void**)&pgh,  g_gh);
    cudaGetSymbolAddress((void**)&py,   g_y);
    cudaGetSymbolAddress((void**)&po,   g_o);
    cudaGetSymbolAddress((void**)&pidx, g_idx);

    // deter = 0
    zero_kernel<<<(B_ * DET_ + 255) / 256, 256>>>(pdet, B_ * DET_);

    // E[b*T+t, h] = embed @ W_obs1[600:,:] + b_obs1   (parallel over all timesteps)
    {
        GArgs g;
        g.A = embed; g.lda = EMB_;
        g.W = W_obs1 + (long)DET_ * HID_; g.ldw = HID_;
        g.add = b_obs1; g.addStride = 0;
        g.C = pE; g.cStride = HID_;
        g.act = 0; g.noise = nullptr; g.onehot = nullptr; g.idxout = nullptr; g.t = 0;
        gemm_k<64><<<dim3((HID_ + 63) / 64, (B_ * T_) / 32, 1), 128>>>(g, g, B_ * T_, HID_, EMB_);
    }

    for (int t = 0; t < T_; t++) {
        // ---- img1: x ----
        img1_kernel<<<B_, 256>>>(action, W_img1, b_img1, px, t, t == 0 ? 1 : 0);

        // ---- GRU gates: gx = x@Wx + b_in ; gh = deter@Wh + b_rec ----
        {
            GArgs a, b;
            a.A = px;   a.lda = HID_; a.W = Wx; a.ldw = G3_;
            a.add = b_in;  a.addStride = 0; a.C = pgx; a.cStride = G3_; a.act = 0;
            a.noise = nullptr; a.onehot = nullptr; a.idxout = nullptr; a.t = t;
            b = a;
            b.A = pdet; b.lda = DET_; b.W = Wh;
            b.add = b_rec; b.C = pgh;
            gemm_k<64><<<dim3((G3_ + 63) / 64, B_ / 32, 2), 128>>>(a, b, B_, G3_, HID_);
        }

        // ---- gate -> deter (also writes deter to out) ----
        gate_kernel<<<(B_ * DET_ + 255) / 256, 256>>>(out, t);

        // ---- y = elu(deter@W_img2+b) ; o = elu(deter@W_obs1[:600] + E[:,t,:]) ----
        {
            GArgs a, b;
            a.A = pdet; a.lda = DET_; a.W = W_img2; a.ldw = HID_;
            a.add = b_img2; a.addStride = 0; a.C = py; a.cStride = HID_; a.act = 1;
            a.noise = nullptr; a.onehot = nullptr; a.idxout = nullptr; a.t = t;
            b = a;
            b.W = W_obs1;
            b.add = pE + (long)t * HID_; b.addStride = (long)T_ * HID_;
            b.C = po;
            gemm_k<32><<<dim3((HID_ + 31) / 32, B_ / 32, 2), 128>>>(a, b, B_, HID_, DET_);
        }

        // ---- logits + fused Gumbel-max sampling (direct to out) ----
        {
            GArgs a, b;
            // prior: logit = y@W_img5 + b_img5; one-hot -> stoch_prior
            a.A = py; a.lda = HID_; a.W = W_img5; a.ldw = SF_;
            a.add = b_img5; a.addStride = 0;
            a.C = out + (long)t * OUTW_ + 2648; a.cStride = (long)T_ * OUTW_; a.act = 0;
            a.noise = n_img; a.onehot = out + (long)t * OUTW_ + 3672;
            a.idxout = nullptr; a.t = t;
            // post: logit = o@W_obs3 + b_obs3; one-hot -> stoch_post; indices -> carry
            b.A = po; b.lda = HID_; b.W = W_obs3; b.ldw = SF_;
            b.add = b_obs3; b.addStride = 0;
            b.C = out + (long)t * OUTW_ + 0; b.cStride = (long)T_ * OUTW_; b.act = 0;
            b.noise = n_obs; b.onehot = out + (long)t * OUTW_ + 1024;
            b.idxout = pidx; b.t = t;
            gemm_k<64><<<dim3(SF_ / 64, B_ / 32, 2), 128>>>(a, b, B_, SF_, HID_);
        }
    }
}

// round 9
// speedup vs baseline: 1.1725x; 1.1725x over previous
#include <cuda_runtime.h>
#include <math.h>

// ---------------- problem constants ----------------
#define B_    256
#define T_    64
#define ACT_  6
#define EMB_  1024
#define S_    32
#define D_    32
#define SF_   1024              // S*D
#define DET_  600
#define HID_  600
#define G3_   1800              // 3*DET
#define OUTW_ 4696              // 4*SF + DET
// out layout per (b,t): [logit_post 0..1024) [stoch_post 1024..2048) [deter 2048..2648)
//                       [logit_prior 2648..3672) [stoch_prior 3672..4696)

__device__ __forceinline__ float eluf(float v) { return v > 0.f ? v : expm1f(v); }

// ---------------- device scratch (no allocs allowed) ----------------
__device__ float g_E[(size_t)B_ * T_ * HID_];   // embed @ W_obs1[600:] + b_obs1
__device__ float g_x[B_ * HID_];
__device__ float g_deter[B_ * DET_];
__device__ float g_gx[2 * B_ * G3_];            // 2 K-split partials
__device__ float g_gh[2 * B_ * G3_];
__device__ float g_y[2 * B_ * HID_];
__device__ float g_o[2 * B_ * HID_];
__device__ float g_lp[4 * (size_t)B_ * SF_];    // prior logit partials (4 splits)
__device__ float g_lq[4 * (size_t)B_ * SF_];    // post  logit partials
__device__ int   g_idx[B_ * S_];

// ---------------- GEMM args ----------------
// C_partial[split] += A' @ W  over this split's k-range, where
//   A' = PRE ? elu(A + A2 + aadd[m*aaddStride + k]) : A
// Unsplit (KS=1) may apply output add/act.
struct GArgs {
    const float* A; int lda;
    const float* A2;                     // second A partial (PRE path)
    const float* aadd; long aaddStride;  // pre-activation add (PRE path)
    const float* W; int ldw;
    const float* add; long addStride;    // output add (nullptr => none)
    float* C; long cStride; long pstride;// partial buffer stride (elements)
    int act;                             // output elu (only unsplit)
};

// ---------------- fp32 GEMM: BM=32, BK=16, 128 threads ----------------
// Double-buffered smem tiles + double-buffered register fragments (R6 core).
// blockIdx.z = gemmIdx * KS + split; split covers a 16-aligned k-chunk.
template<int BN, bool PRE>
__global__ __launch_bounds__(128, 6) void gemm_k(GArgs ga, GArgs gb, int M, int N, int K, int KS)
{
    constexpr int TN = BN / 16;         // 4 or 2
    constexpr int ASTR = 36;
    constexpr int WSTR = BN + 4;
    constexpr int WL = BN / 32;

    const int gi = blockIdx.z / KS;
    const int split = blockIdx.z - gi * KS;
    const GArgs g = gi ? gb : ga;

    const int kchunk = ((((K + KS - 1) / KS) + 15) >> 4) << 4;
    const int kbeg = split * kchunk;
    int klen = K - kbeg; if (klen > kchunk) klen = kchunk;

    __shared__ __align__(16) float As[2][16][ASTR];   // As[k][m] (transposed)
    __shared__ __align__(16) float Ws[2][16][WSTR];   // Ws[k][n]

    const int tid = threadIdx.x;
    const int m0 = blockIdx.y * 32;
    const int n0 = blockIdx.x * BN;

    const int am = tid >> 2;            // 0..31
    const int ak = (tid & 3) * 4;       // 0,4,8,12
    const int tm = (tid >> 4) * 4;      // 0..28
    const int tn = (tid & 15) * TN;     // 0..BN-TN

    const int ntiles = (klen + 15) >> 4;

    float4 rA;
    float4 rW[WL];
    const float* Abase  = g.A + (long)(m0 + am) * g.lda + kbeg + ak;
    const float* A2base = PRE ? g.A2 + (long)(m0 + am) * g.lda + kbeg + ak : nullptr;
    const float* Adbase = PRE ? g.aadd + (long)(m0 + am) * g.aaddStride + kbeg + ak : nullptr;

    auto loadTile = [&](int kt) {
        const int k0 = kt << 4;
        if (k0 + ak < klen) {
            float4 a = *(const float4*)(Abase + k0);
            if (PRE) {
                float4 a2 = *(const float4*)(A2base + k0);
                float4 ad = *(const float4*)(Adbase + k0);
                a.x = eluf(a.x + a2.x + ad.x);
                a.y = eluf(a.y + a2.y + ad.y);
                a.z = eluf(a.z + a2.z + ad.z);
                a.w = eluf(a.w + a2.w + ad.w);
            }
            rA = a;
        } else rA = make_float4(0.f, 0.f, 0.f, 0.f);
#pragma unroll
        for (int l = 0; l < WL; l++) {
            int idx = tid + l * 128;
            int wk = idx / (BN / 4);
            int wn = (idx % (BN / 4)) * 4;
            int nn = n0 + wn;
            if (k0 + wk < klen && nn < N)
                rW[l] = *(const float4*)(g.W + (long)(kbeg + k0 + wk) * g.ldw + nn);
            else
                rW[l] = make_float4(0.f, 0.f, 0.f, 0.f);
        }
    };
    auto storeTile = [&](int buf) {
        As[buf][ak + 0][am] = rA.x;
        As[buf][ak + 1][am] = rA.y;
        As[buf][ak + 2][am] = rA.z;
        As[buf][ak + 3][am] = rA.w;
#pragma unroll
        for (int l = 0; l < WL; l++) {
            int idx = tid + l * 128;
            int wk = idx / (BN / 4);
            int wn = (idx % (BN / 4)) * 4;
            *(float4*)&Ws[buf][wk][wn] = rW[l];
        }
    };

    float acc[4][TN];
#pragma unroll
    for (int i = 0; i < 4; i++)
#pragma unroll
        for (int j = 0; j < TN; j++) acc[i][j] = 0.f;

    float fa[2][4];
    float fb[2][TN];

    loadTile(0);
    storeTile(0);
    __syncthreads();

    int cur = 0;

    auto ldfrag = [&](int buf, int k) {
        float4 a4 = *(const float4*)&As[cur][k][tm];
        fa[buf][0] = a4.x; fa[buf][1] = a4.y; fa[buf][2] = a4.z; fa[buf][3] = a4.w;
        if (TN == 4) {
            float4 b4 = *(const float4*)&Ws[cur][k][tn];
            fb[buf][0] = b4.x; fb[buf][1] = b4.y; fb[buf][2] = b4.z; fb[buf][3] = b4.w;
        } else {
            float2 b2 = *(const float2*)&Ws[cur][k][tn];
            fb[buf][0] = b2.x; fb[buf][1] = b2.y;
        }
    };

    ldfrag(0, 0);

    for (int kt = 0; kt < ntiles; kt++) {
        const bool more = (kt + 1 < ntiles);
        if (more) loadTile(kt + 1);     // global loads overlap compute below
#pragma unroll
        for (int k = 0; k < 16; k++) {
            const int cb = k & 1;
            if (k < 15) ldfrag(cb ^ 1, k + 1);   // prefetch next fragments
#pragma unroll
            for (int i = 0; i < 4; i++)
#pragma unroll
                for (int j = 0; j < TN; j++)
                    acc[i][j] = fmaf(fa[cb][i], fb[cb][j], acc[i][j]);
        }
        if (more) {
            storeTile(cur ^ 1);
            __syncthreads();
            cur ^= 1;
            ldfrag(0, 0);
        }
    }

    // ---- epilogue: optional add/act, store to this split's partial buffer ----
    float* Cp = g.C + (long)split * g.pstride;
#pragma unroll
    for (int i = 0; i < 4; i++) {
        const long m = m0 + tm + i;
#pragma unroll
        for (int j = 0; j < TN; j++) {
            int n = n0 + tn + j;
            if (n < N) {
                float v = acc[i][j];
                if (g.add) v += g.add[m * g.addStride + n];
                if (g.act) v = eluf(v);
                Cp[m * g.cStride + n] = v;
            }
        }
    }
}

// ---------------- step kernels ----------------

// x[b,h] = elu( gather32(W_img1, idx) + action@W_img1[1024:] + b_img1 )
__global__ __launch_bounds__(256) void img1_kernel(const float* __restrict__ action,
                                                   const float* __restrict__ W1,
                                                   const float* __restrict__ b1,
                                                   float* __restrict__ x,
                                                   int t, int first)
{
    const int b = blockIdx.x;
    const int tid = threadIdx.x;
    __shared__ int   sidx[S_];
    __shared__ float sact[ACT_];
    if (!first && tid < S_) sidx[tid] = g_idx[b * S_ + tid];
    if (tid < ACT_) sact[tid] = action[((long)b * T_ + t) * ACT_ + tid];
    __syncthreads();
    for (int h = tid; h < HID_; h += 256) {
        float acc = b1[h];
#pragma unroll
        for (int j = 0; j < ACT_; j++)
            acc = fmaf(sact[j], W1[(1024 + j) * HID_ + h], acc);
        if (!first) {
#pragma unroll 4
            for (int gg = 0; gg < S_; gg++)
                acc += W1[(gg * D_ + sidx[gg]) * HID_ + h];
        }
        x[b * HID_ + h] = eluf(acc);
    }
}

// GRU gate from 2 K-split partials each of gx/gh, with biases applied here.
__global__ __launch_bounds__(256) void gate_kernel(float* __restrict__ out,
                                                   const float* __restrict__ b_in,
                                                   const float* __restrict__ b_rec,
                                                   int t)
{
    int i = blockIdx.x * 256 + threadIdx.x;
    if (i >= B_ * DET_) return;
    int b = i / DET_, j = i - b * DET_;
    const long o0 = (long)b * G3_;
    const long P = (long)B_ * G3_;
    float xz = g_gx[o0 + j]        + g_gx[P + o0 + j]        + b_in[j];
    float hz = g_gh[o0 + j]        + g_gh[P + o0 + j]        + b_rec[j];
    float xr = g_gx[o0 + 600 + j]  + g_gx[P + o0 + 600 + j]  + b_in[600 + j];
    float hr = g_gh[o0 + 600 + j]  + g_gh[P + o0 + 600 + j]  + b_rec[600 + j];
    float xh = g_gx[o0 + 1200 + j] + g_gx[P + o0 + 1200 + j] + b_in[1200 + j];
    float hh = g_gh[o0 + 1200 + j] + g_gh[P + o0 + 1200 + j] + b_rec[1200 + j];
    float z = 1.0f / (1.0f + expf(-(xz + hz)));
    float r = 1.0f / (1.0f + expf(-(xr + hr)));
    float cand = tanhf(fmaf(r, hh, xh));
    float d = g_deter[i];
    float dn = z * d + (1.0f - z) * cand;
    g_deter[i] = dn;
    out[(long)b * (T_ * OUTW_) + (long)t * OUTW_ + 2048 + j] = dn;
}

// Sum 4 logit partials + bias -> out logit; Gumbel-max -> one-hot (+carry idx).
__global__ __launch_bounds__(256) void sample_kernel(float* __restrict__ out,
                                                     const float* __restrict__ noise_img,
                                                     const float* __restrict__ noise_obs,
                                                     const float* __restrict__ b_img5,
                                                     const float* __restrict__ b_obs3,
                                                     int t)
{
    const int lane = threadIdx.x & 31;
    const int wrp = threadIdx.x >> 5;
    const int gid = blockIdx.x * 8 + wrp;        // 0..8191
    const int b = gid >> 5;
    const int s = gid & 31;
    const int post = blockIdx.y;                 // 0 prior, 1 post
    const float* lp = post ? g_lq : g_lp;
    const float* bias = post ? b_obs3 : b_img5;
    const float* noise = post ? noise_obs : noise_img;
    const int col = s * D_ + lane;
    const long PS = (long)B_ * SF_;
    const long off = (long)b * SF_ + col;

    float v = lp[off] + lp[PS + off] + lp[2 * PS + off] + lp[3 * PS + off] + bias[col];

    const long row = (long)b * (T_ * OUTW_) + (long)t * OUTW_;
    out[row + (post ? 0 : 2648) + col] = v;

    float gv = v + noise[(((long)b * T_ + t) * S_ + s) * D_ + lane];
    int bi = lane;
#pragma unroll
    for (int o = 16; o > 0; o >>= 1) {
        float ov = __shfl_xor_sync(0xffffffffu, gv, o);
        int   oi = __shfl_xor_sync(0xffffffffu, bi, o);
        if (ov > gv || (ov == gv && oi < bi)) { gv = ov; bi = oi; }
    }
    out[row + (post ? 1024 : 3672) + col] = (lane == bi) ? 1.f : 0.f;
    if (post && lane == 0) g_idx[b * S_ + s] = bi;
}

__global__ void zero_kernel(float* p, int n)
{
    int i = blockIdx.x * 256 + threadIdx.x;
    if (i < n) p[i] = 0.0f;
}

// ---------------- host ----------------
extern "C" void kernel_launch(void* const* d_in, const int* in_sizes, int n_in,
                              void* d_out, int out_size)
{
    (void)in_sizes; (void)n_in; (void)out_size;
    const float* action  = (const float*)d_in[0];
    const float* embed   = (const float*)d_in[1];
    const float* n_img   = (const float*)d_in[2];
    const float* n_obs   = (const float*)d_in[3];
    const float* W_img1  = (const float*)d_in[4];
    const float* b_img1  = (const float*)d_in[5];
    const float* Wx      = (const float*)d_in[6];
    const float* Wh      = (const float*)d_in[7];
    const float* b_in    = (const float*)d_in[8];
    const float* b_rec   = (const float*)d_in[9];
    const float* W_img2  = (const float*)d_in[10];
    const float* b_img2  = (const float*)d_in[11];
    const float* W_img5  = (const float*)d_in[12];
    const float* b_img5  = (const float*)d_in[13];
    const float* W_obs1  = (const float*)d_in[14];
    const float* b_obs1  = (const float*)d_in[15];
    const float* W_obs3  = (const float*)d_in[16];
    const float* b_obs3  = (const float*)d_in[17];
    float* out = (float*)d_out;

    float *pE, *px, *pdet, *pgx, *pgh, *py, *po, *plp, *plq;
    cudaGetSymbolAddress((void**)&pE,   g_E);
    cudaGetSymbolAddress((void**)&px,   g_x);
    cudaGetSymbolAddress((void**)&pdet, g_deter);
    cudaGetSymbolAddress((void**)&pgx,  g_gx);
    cudaGetSymbolAddress((void**)&pgh,  g_gh);
    cudaGetSymbolAddress((void**)&py,   g_y);
    cudaGetSymbolAddress((void**)&po,   g_o);
    cudaGetSymbolAddress((void**)&plp,  g_lp);
    cudaGetSymbolAddress((void**)&plq,  g_lq);
    int* pidx;
    cudaGetSymbolAddress((void**)&pidx, g_idx);

    // deter = 0
    zero_kernel<<<(B_ * DET_ + 255) / 256, 256>>>(pdet, B_ * DET_);

    // E[b*T+t, h] = embed @ W_obs1[600:,:] + b_obs1   (parallel over all timesteps)
    {
        GArgs g = {};
        g.A = embed; g.lda = EMB_;
        g.W = W_obs1 + (long)DET_ * HID_; g.ldw = HID_;
        g.add = b_obs1; g.addStride = 0;
        g.C = pE; g.cStride = HID_; g.pstride = 0;
        g.act = 0;
        gemm_k<64, false><<<dim3((HID_ + 63) / 64, (B_ * T_) / 32, 1), 128>>>(
            g, g, B_ * T_, HID_, EMB_, 1);
    }

    for (int t = 0; t < T_; t++) {
        // ---- img1: x ----
        img1_kernel<<<B_, 256>>>(action, W_img1, b_img1, px, t, t == 0 ? 1 : 0);

        // ---- GRU gate pre-acts, K split 2 (biases applied in gate) ----
        {
            GArgs a = {}, b = {};
            a.A = px;   a.lda = HID_; a.W = Wx; a.ldw = G3_;
            a.add = nullptr; a.C = pgx; a.cStride = G3_; a.pstride = (long)B_ * G3_; a.act = 0;
            b = a;
            b.A = pdet; b.lda = DET_; b.W = Wh; b.C = pgh;
            gemm_k<64, false><<<dim3((G3_ + 63) / 64, B_ / 32, 4), 128>>>(
                a, b, B_, G3_, HID_, 2);
        }

        // ---- gate -> deter (sums partials + biases; writes deter to out) ----
        gate_kernel<<<(B_ * DET_ + 255) / 256, 256>>>(out, b_in, b_rec, t);

        // ---- y/o pre-acts, K split 2 (elu + adds applied in logits A-load) ----
        {
            GArgs a = {}, b = {};
            a.A = pdet; a.lda = DET_; a.W = W_img2; a.ldw = HID_;
            a.add = nullptr; a.C = py; a.cStride = HID_; a.pstride = (long)B_ * HID_; a.act = 0;
            b = a;
            b.W = W_obs1; b.C = po;
            gemm_k<32, false><<<dim3((HID_ + 31) / 32, B_ / 32, 4), 128>>>(
                a, b, B_, HID_, DET_, 2);
        }

        // ---- logits, K split 4; A' = elu(partials + add) computed in-load ----
        {
            GArgs a = {}, b = {};
            a.A = py; a.lda = HID_; a.A2 = py + (long)B_ * HID_;
            a.aadd = b_img2; a.aaddStride = 0;
            a.W = W_img5; a.ldw = SF_;
            a.add = nullptr;
            a.C = plp; a.cStride = SF_; a.pstride = (long)B_ * SF_; a.act = 0;
            b.A = po; b.lda = HID_; b.A2 = po + (long)B_ * HID_;
            b.aadd = pE + (long)t * HID_; b.aaddStride = (long)T_ * HID_;
            b.W = W_obs3; b.ldw = SF_;
            b.add = nullptr;
            b.C = plq; b.cStride = SF_; b.pstride = (long)B_ * SF_; b.act = 0;
            gemm_k<64, true><<<dim3(SF_ / 64, B_ / 32, 8), 128>>>(
                a, b, B_, SF_, HID_, 4);
        }

        // ---- reduce logit partials + bias -> out; Gumbel-max sample ----
        sample_kernel<<<dim3((B_ * S_) / 8, 2), 256>>>(out, n_img, n_obs, b_img5, b_obs3, t);
    }
}